// round 14
// baseline (speedup 1.0000x reference)
#include <cuda_runtime.h>
#include <climits>
#include <cstring>
#include <cstdint>

#define HH 6144
#define WW 6144
#define G  50

#define TPB    256
#define SLAB   64
#define NSLAB  (HH / SLAB)     // 96
#define STRIPW 512             // TPB * 2 columns
#define STG_ROWS 8
#define NB     (SLAB / STG_ROWS)   // 8
#define ROW_BYTES (STRIPW * 4)     // 2048
#define STG_BYTES (STG_ROWS * ROW_BYTES)  // 16384
#define EVSTRIDE 104           // 100 events + 4 sentinel pads

// -------- device scratch (no allocs allowed) --------
__device__ int    g_ev[WW * EVSTRIDE];   // per-column merged events: (row<<1)|is_h, INT_MAX sentinels
__device__ int    g_slab[NSLAB * WW];    // per-(slab,column) state at slab start: (h<<6)|v ; event ptr = h+v
__device__ double g_binh[G];
__device__ double g_binv[G];
__device__ int    g_dummy;

// ---------------- setup: one thread per (x,g); type-bit merged event stream ----------------
__global__ void setup_kernel(const float* rho_max_p, const float* rho_min_p,
                             const float* thmin_p,  const float* thmax_p,
                             const float* tvmin_p,  const float* tvmax_p) {
    __shared__ float Th[G], Ch[G], Av[G], Bv[G];
    __shared__ int svv[4][64], shh[4][64];

    int g   = threadIdx.x;          // 0..63
    int ci  = threadIdx.y;          // 0..3  column within block
    int lin = ci * 64 + g;

    if (lin < G) {
        float rho_max = *rho_max_p, rho_min = *rho_min_p;
        float thmin = *thmin_p, thmax = *thmax_p;
        float tvmin = *tvmin_p, tvmax = *tvmax_p;
        float t   = (float)lin / 49.0f;
        float thg = __fadd_rn(thmin,   __fmul_rn(__fadd_rn(thmax, -thmin), t));
        float tvg = __fadd_rn(tvmin,   __fmul_rn(__fadd_rn(tvmax, -tvmin), t));
        float rg  = __fadd_rn(rho_max, __fmul_rn(__fadd_rn(rho_min, -rho_max), t));
        Th[lin] = tanf(thg);
        Ch[lin] = rg / cosf(thg);
        Av[lin] = tanf(tvg);
        Bv[lin] = rg / sinf(tvg);
        if (blockIdx.x == 0) { g_binh[lin] = 0.0; g_binv[lin] = 0.0; }
    }
    __syncthreads();

    int x  = blockIdx.x * 4 + ci;
    int xe = x; if (xe < 1) xe = 1; if (xe > WW - 2) xe = WW - 2;
    float xef = (float)xe;

    int vval = INT_MAX, hval = INT_MAX;
    if (g < G) {
        // vertical event row: y_g(xe) = round(-xe/tan(tv) + rho/sin(tv)), clip >= 0;
        // rows >= H-1 never trigger (y_eff <= H-2)
        float val = __fadd_rn(__fdiv_rn(-(float)xe, Av[g]), Bv[g]);
        int iv = (int)rintf(val);
        if (iv < 0) iv = 0;
        vval = (iv >= HH - 1) ? INT_MAX : iv;

        // horizontal: P(y) := round(-y*T + C) <= xe, monotone false->true in y over [1, H-2]
        float T = Th[g], C = Ch[g];
        float v1 = rintf(__fadd_rn(-T, C));
        if (v1 <= xef) {
            hval = 1;  // "base" line: true from the start -> event at row 1
        } else {
            float vH = rintf(__fadd_rn(__fmul_rn(-(float)(HH - 2), T), C));
            if (vH <= xef) {
                int lo = 1, hi = HH - 2;                  // P(lo)=F, P(hi)=T
                while (hi - lo > 1) {
                    int mid = (lo + hi) >> 1;
                    float vm = rintf(__fadd_rn(__fmul_rn(-(float)mid, T), C));
                    if (vm <= xef) hi = mid; else lo = mid;
                }
                hval = hi;
            }
        }
        svv[ci][g] = vval;
        shh[ci][g] = hval;
    }
    __syncthreads();

    if (g < G) {
        // merged ranks: key_v = (row<<1), key_h = (row<<1)|1; ties broken by j<g
        int pos_v = 0, pos_h = 0;
        #pragma unroll 10
        for (int j = 0; j < G; ++j) {
            int vj = svv[ci][j], hj = shh[ci][j];
            pos_v += (vj < vval) || (vj == vval && j < g);  // v vs v
            pos_v += (hj < vval);                           // h-key < v-key  <=>  hj <  vval
            pos_h += (hj < hval) || (hj == hval && j < g);  // h vs h
            pos_h += (vj <= hval);                          // v-key < h-key  <=>  vj <= hval
        }
        int ev_v = (vval >= HH) ? INT_MAX : (vval << 1);
        int ev_h = (hval >= HH) ? INT_MAX : ((hval << 1) | 1);
        g_ev[x * EVSTRIDE + pos_v] = ev_v;
        g_ev[x * EVSTRIDE + pos_h] = ev_h;
    } else if (g < G + 4) {
        g_ev[x * EVSTRIDE + 100 + (g - G)] = INT_MAX;  // sentinel pad
    }

    // per-slab starting state (slab 0 -> row 1, edge fix); NSLAB=96 -> two passes of 64 threads
    for (int s = g; s < NSLAB; s += 64) {
        int y0p = (s == 0) ? 1 : s * SLAB;
        int ph = 0, pv = 0;
        #pragma unroll 10
        for (int j = 0; j < G; ++j) {
            ph += (shh[ci][j] <= y0p);
            pv += (svv[ci][j] <= y0p);
        }
        g_slab[s * WW + x] = (ph << 6) | pv;
    }
}

// ---------------- dummy kernel: ncu launch-index steering ----------------
__global__ void dummy_kernel() { if (blockIdx.x == 1u << 30) g_dummy = 1; }

// ---------------- main pass: cp.async (LDGSTS) double-buffered smem streaming --------
__device__ __forceinline__ uint32_t smem_u32(const void* p) {
    uint32_t a;
    asm("{ .reg .u64 t; cvta.to.shared.u64 t, %1; cvt.u32.u64 %0, t; }" : "=r"(a) : "l"(p));
    return a;
}

__global__ void __launch_bounds__(TPB, 6) main_kernel(const float* __restrict__ sp) {
    __shared__ float sh[G], sv[G];
    __shared__ __align__(16) char stagebuf[2 * STG_BYTES];

    int tid = threadIdx.x;
    if (tid < G) { sh[tid] = 0.f; sv[tid] = 0.f; }

    const int c0 = blockIdx.x * STRIPW + tid * 2;
    const int y0 = blockIdx.y * SLAB;
    const char* gsrc = reinterpret_cast<const char*>(sp)
                     + (size_t)y0 * ROW_BYTES * (WW / STRIPW) // y0 * WW * 4
                     + (size_t)blockIdx.x * STRIPW * 4;
    // NOTE: WW*4 == ROW_BYTES * (WW/STRIPW) == 24576

    const uint32_t sstage = smem_u32(stagebuf);
    const int row_off  = (tid * 16) >> 11;      // 0 or 1
    const int col_byte = (tid * 16) & 2047;

    // issue one stage: 4 x cp.async.cg of 16B per thread (fully coalesced)
    #define ISSUE_STAGE(slot, krow)                                                \
        {                                                                          \
            uint32_t sb_ = sstage + (slot) * STG_BYTES + row_off * 2048 + col_byte;\
            const char* gb_ = gsrc + (size_t)((krow) + row_off) * 24576 + col_byte;\
            _Pragma("unroll")                                                      \
            for (int i_ = 0; i_ < 4; ++i_) {                                       \
                asm volatile("cp.async.cg.shared.global [%0], [%1], 16;"           \
                             :: "r"(sb_ + i_ * 4096), "l"(gb_ + (size_t)i_ * 2 * 24576) : "memory"); \
            }                                                                      \
            asm volatile("cp.async.commit_group;" ::: "memory");                   \
        }

    // prologue: stages 0 and 1 in flight
    ISSUE_STAGE(0, 0)
    ISSUE_STAGE(1, STG_ROWS)

    // walker init (2 columns per thread)
    int hcur[2], vcur[2], eptr[2], e0[2], e1[2];
    #pragma unroll
    for (int c = 0; c < 2; ++c) {
        int x = c0 + c;
        int s = g_slab[blockIdx.y * WW + x];
        hcur[c] = s >> 6; vcur[c] = s & 63;
        int p0 = hcur[c] + vcur[c];            // #events already applied
        eptr[c] = p0;
        e0[c] = g_ev[x * EVSTRIDE + p0];
        e1[c] = g_ev[x * EVSTRIDE + p0 + 1];
    }
    int nxtmin = min(e0[0] >> 1, e0[1] >> 1);

    unsigned long long acc0 = 0ull, acc1 = 0ull;   // packed f32x2, alternating rows

    #pragma unroll 1
    for (int k = 0; k < NB; ++k) {
        if (k + 1 < NB) { asm volatile("cp.async.wait_group 1;" ::: "memory"); }
        else            { asm volatile("cp.async.wait_group 0;" ::: "memory"); }
        __syncthreads();

        const char* sdata = stagebuf + (k & 1) * STG_BYTES + tid * 8;
        int yb = y0 + k * STG_ROWS;

        if (nxtmin >= yb + STG_ROWS) {
            // fast path: no events for this thread's columns in this stage
            #pragma unroll
            for (int r = 0; r < STG_ROWS; r += 2) {
                unsigned long long ua = *reinterpret_cast<const unsigned long long*>(sdata + r * ROW_BYTES);
                unsigned long long ub = *reinterpret_cast<const unsigned long long*>(sdata + (r + 1) * ROW_BYTES);
                asm("add.rn.f32x2 %0, %0, %1;" : "+l"(acc0) : "l"(ua));
                asm("add.rn.f32x2 %0, %0, %1;" : "+l"(acc1) : "l"(ub));
            }
        } else {
            #pragma unroll
            for (int r = 0; r < STG_ROWS; ++r) {
                int yy = yb + r;
                if (nxtmin <= yy) {
                    float2 f0, f1;
                    memcpy(&f0, &acc0, 8); memcpy(&f1, &acc1, 8);
                    float a[2] = { f0.x + f1.x, f0.y + f1.y };
                    nxtmin = INT_MAX;
                    #pragma unroll
                    for (int c = 0; c < 2; ++c) {
                        int er = e0[c] >> 1;
                        if (er <= yy) {
                            if (hcur[c] < G) atomicAdd(&sh[hcur[c]], a[c]);
                            if (vcur[c] < G) atomicAdd(&sv[vcur[c]], a[c]);
                            a[c] = 0.f;
                            do {
                                if (e0[c] & 1) hcur[c]++; else vcur[c]++;
                                e0[c] = e1[c];
                                eptr[c]++;
                                e1[c] = g_ev[(c0 + c) * EVSTRIDE + eptr[c] + 1];
                                er = e0[c] >> 1;
                            } while (er <= yy);
                        }
                        nxtmin = min(nxtmin, er);
                    }
                    float2 n0 = make_float2(a[0], a[1]);
                    memcpy(&acc0, &n0, 8);
                    acc1 = 0ull;
                }
                unsigned long long u = *reinterpret_cast<const unsigned long long*>(sdata + r * ROW_BYTES);
                if (r & 1) { asm("add.rn.f32x2 %0, %0, %1;" : "+l"(acc1) : "l"(u)); }
                else       { asm("add.rn.f32x2 %0, %0, %1;" : "+l"(acc0) : "l"(u)); }
            }
        }

        __syncthreads();   // all threads done with this slot before refilling it
        if (k + 2 < NB) ISSUE_STAGE(k & 1, (k + 2) * STG_ROWS)
    }
    #undef ISSUE_STAGE

    // residual flush
    {
        float2 f0, f1;
        memcpy(&f0, &acc0, 8); memcpy(&f1, &acc1, 8);
        float a[2] = { f0.x + f1.x, f0.y + f1.y };
        #pragma unroll
        for (int c = 0; c < 2; ++c) {
            if (hcur[c] < G) atomicAdd(&sh[hcur[c]], a[c]);
            if (vcur[c] < G) atomicAdd(&sv[vcur[c]], a[c]);
        }
    }
    __syncthreads();
    if (tid < G) {
        atomicAdd(&g_binh[tid], (double)sh[tid]);
        atomicAdd(&g_binv[tid], (double)sv[tid]);
    }
}

// ---------------- final: 64-thread scan + percentiles + intersections ----------------
__device__ __forceinline__ float lin_f(float a, float b, int i) {
    float t = (float)i / 49.0f;
    return __fadd_rn(a, __fmul_rn(__fadd_rn(b, -a), t));
}

__global__ void final_kernel(float* out,
                             const float* rho_max_p, const float* rho_min_p,
                             const float* thmin_p,  const float* thmax_p,
                             const float* tvmin_p,  const float* tvmax_p) {
    __shared__ double s_h[64], s_v[64];
    int t = threadIdx.x;  // 64 threads
    s_h[t] = (t < G) ? g_binh[t] : 0.0;
    s_v[t] = (t < G) ? g_binv[t] : 0.0;
    __syncthreads();
    #pragma unroll
    for (int off = 1; off < 64; off <<= 1) {
        double ah = (t >= off) ? s_h[t - off] : 0.0;
        double av = (t >= off) ? s_v[t - off] : 0.0;
        __syncthreads();
        s_h[t] += ah; s_v[t] += av;
        __syncthreads();
    }
    if (t != 0) return;

    double tot_h = s_h[G - 1], tot_v = s_v[G - 1];

    int lower_h = 0, upper_h, lower_v = 0, upper_v;
    for (int s = 0; s < G; ++s) { if (s_h[s] / tot_h >= 0.01) { lower_h = s; break; } }
    {
        int j = 0;
        for (int jj = 0; jj < G; ++jj) { if (s_h[G - 1 - jj] / tot_h <= 0.99) { j = jj; break; } }
        upper_h = (G - 1) - j + 2;
    }
    for (int s = 0; s < G; ++s) { if (s_v[s] / tot_v >= 0.01) { lower_v = s; break; } }
    {
        int j = 0;
        for (int jj = 0; jj < G; ++jj) { if (s_v[G - 1 - jj] / tot_v <= 0.99) { j = jj; break; } }
        upper_v = (G - 1) - j + 2;
    }

    float rho_max = *rho_max_p, rho_min = *rho_min_p;
    float thmin = *thmin_p, thmax = *thmax_p;
    float tvmin = *tvmin_p, tvmax = *tvmax_p;

    int i_lh = ((G - lower_h) % G + G) % G;
    int i_uh = ((G - upper_h) % G + G) % G;
    int i_lv = ((G - lower_v) % G + G) % G;
    int i_uv = ((G - upper_v) % G + G) % G;

    float r_min_h = lin_f(rho_max, rho_min, i_lh), t_min_h = lin_f(thmin, thmax, i_lh);
    float r_max_h = lin_f(rho_max, rho_min, i_uh), t_max_h = lin_f(thmin, thmax, i_uh);
    float r_min_v = lin_f(rho_max, rho_min, i_lv), t_min_v = lin_f(tvmin, tvmax, i_lv);
    float r_max_v = lin_f(rho_max, rho_min, i_uv), t_max_v = lin_f(tvmin, tvmax, i_uv);

    float r1, t1, r2, t2;
    #define ISECT(o)                                                        \
        {                                                                   \
            float det = cosf(t1) * sinf(t2) - cosf(t2) * sinf(t1);          \
            out[(o) * 2 + 0] = (r1 * sinf(t2) - r2 * sinf(t1)) / det;       \
            out[(o) * 2 + 1] = (r2 * cosf(t1) - r1 * cosf(t2)) / det;       \
        }
    r1 = r_min_h; t1 = t_min_h; r2 = r_min_v; t2 = t_min_v; ISECT(0)  // top-left
    r1 = r_max_h; t1 = t_max_h; r2 = r_min_v; t2 = t_min_v; ISECT(1)  // top-right
    r1 = r_max_h; t1 = t_max_h; r2 = r_max_v; t2 = t_max_v; ISECT(2)  // bottom-right
    r1 = r_min_h; t1 = t_min_h; r2 = r_max_v; t2 = t_max_v; ISECT(3)  // bottom-left
    #undef ISECT
}

// ---------------- launch ----------------
extern "C" void kernel_launch(void* const* d_in, const int* in_sizes, int n_in,
                              void* d_out, int out_size) {
    const float* sp    = (const float*)d_in[0];
    const float* rmax  = (const float*)d_in[1];
    const float* rmin  = (const float*)d_in[2];
    const float* thmin = (const float*)d_in[3];
    const float* thmax = (const float*)d_in[4];
    const float* tvmin = (const float*)d_in[5];
    const float* tvmax = (const float*)d_in[6];

    // 6 launches/call; main at position 3 so profiled index {9,15} -> main_kernel
    dim3 sblk(64, 4);
    setup_kernel<<<WW / 4, sblk>>>(rmax, rmin, thmin, thmax, tvmin, tvmax);   // pos 0
    dummy_kernel<<<1, 32>>>();                                                // pos 1
    dummy_kernel<<<1, 32>>>();                                                // pos 2
    dim3 grid(WW / STRIPW, HH / SLAB);
    main_kernel<<<grid, TPB>>>(sp);                                           // pos 3
    final_kernel<<<1, 64>>>((float*)d_out, rmax, rmin, thmin, thmax, tvmin, tvmax); // pos 4
    dummy_kernel<<<1, 32>>>();                                                // pos 5
}

// round 15
// speedup vs baseline: 1.2105x; 1.2105x over previous
#include <cuda_runtime.h>
#include <climits>
#include <cstring>
#include <cstdint>

#define HH 6144
#define WW 6144
#define G  50

#define TPB    256
#define SLAB   64
#define NSLAB  (HH / SLAB)     // 96
#define STRIPW 512             // TPB * 2 columns
#define BATCH  8
#define NB     (SLAB / BATCH)  // 8
#define EVSTRIDE 104           // 100 events + 4 sentinel pads

// -------- device scratch (no allocs allowed) --------
__device__ int    g_ev[WW * EVSTRIDE];   // per-column merged events: (row<<1)|is_h, INT_MAX sentinels
__device__ int    g_slab[NSLAB * WW];    // per-(slab,column) state at slab start: (h<<6)|v ; event ptr = h+v
__device__ double g_binh[G];
__device__ double g_binv[G];
__device__ int    g_dummy;

// ---------------- setup: one thread per (x,g); type-bit merged event stream ----------------
__global__ void setup_kernel(const float* rho_max_p, const float* rho_min_p,
                             const float* thmin_p,  const float* thmax_p,
                             const float* tvmin_p,  const float* tvmax_p) {
    __shared__ float Th[G], Ch[G], Av[G], Bv[G];
    __shared__ int svv[4][64], shh[4][64];

    int g   = threadIdx.x;          // 0..63
    int ci  = threadIdx.y;          // 0..3  column within block
    int lin = ci * 64 + g;

    if (lin < G) {
        float rho_max = *rho_max_p, rho_min = *rho_min_p;
        float thmin = *thmin_p, thmax = *thmax_p;
        float tvmin = *tvmin_p, tvmax = *tvmax_p;
        float t   = (float)lin / 49.0f;
        float thg = __fadd_rn(thmin,   __fmul_rn(__fadd_rn(thmax, -thmin), t));
        float tvg = __fadd_rn(tvmin,   __fmul_rn(__fadd_rn(tvmax, -tvmin), t));
        float rg  = __fadd_rn(rho_max, __fmul_rn(__fadd_rn(rho_min, -rho_max), t));
        Th[lin] = tanf(thg);
        Ch[lin] = rg / cosf(thg);
        Av[lin] = tanf(tvg);
        Bv[lin] = rg / sinf(tvg);
        if (blockIdx.x == 0) { g_binh[lin] = 0.0; g_binv[lin] = 0.0; }
    }
    __syncthreads();

    int x  = blockIdx.x * 4 + ci;
    int xe = x; if (xe < 1) xe = 1; if (xe > WW - 2) xe = WW - 2;
    float xef = (float)xe;

    int vval = INT_MAX, hval = INT_MAX;
    if (g < G) {
        // vertical event row: y_g(xe) = round(-xe/tan(tv) + rho/sin(tv)), clip >= 0;
        // rows >= H-1 never trigger (y_eff <= H-2)
        float val = __fadd_rn(__fdiv_rn(-(float)xe, Av[g]), Bv[g]);
        int iv = (int)rintf(val);
        if (iv < 0) iv = 0;
        vval = (iv >= HH - 1) ? INT_MAX : iv;

        // horizontal: P(y) := round(-y*T + C) <= xe, monotone false->true in y over [1, H-2]
        float T = Th[g], C = Ch[g];
        float v1 = rintf(__fadd_rn(-T, C));
        if (v1 <= xef) {
            hval = 1;  // "base" line: true from the start -> event at row 1
        } else {
            float vH = rintf(__fadd_rn(__fmul_rn(-(float)(HH - 2), T), C));
            if (vH <= xef) {
                int lo = 1, hi = HH - 2;                  // P(lo)=F, P(hi)=T
                while (hi - lo > 1) {
                    int mid = (lo + hi) >> 1;
                    float vm = rintf(__fadd_rn(__fmul_rn(-(float)mid, T), C));
                    if (vm <= xef) hi = mid; else lo = mid;
                }
                hval = hi;
            }
        }
        svv[ci][g] = vval;
        shh[ci][g] = hval;
    }
    __syncthreads();

    if (g < G) {
        // merged ranks: key_v = (row<<1), key_h = (row<<1)|1; ties broken by j<g
        int pos_v = 0, pos_h = 0;
        #pragma unroll 10
        for (int j = 0; j < G; ++j) {
            int vj = svv[ci][j], hj = shh[ci][j];
            pos_v += (vj < vval) || (vj == vval && j < g);  // v vs v
            pos_v += (hj < vval);                           // h-key < v-key  <=>  hj <  vval
            pos_h += (hj < hval) || (hj == hval && j < g);  // h vs h
            pos_h += (vj <= hval);                          // v-key < h-key  <=>  vj <= hval
        }
        int ev_v = (vval >= HH) ? INT_MAX : (vval << 1);
        int ev_h = (hval >= HH) ? INT_MAX : ((hval << 1) | 1);
        g_ev[x * EVSTRIDE + pos_v] = ev_v;
        g_ev[x * EVSTRIDE + pos_h] = ev_h;
    } else if (g < G + 4) {
        g_ev[x * EVSTRIDE + 100 + (g - G)] = INT_MAX;  // sentinel pad
    }

    // per-slab starting state (slab 0 -> row 1, edge fix); NSLAB=96 -> two passes of 64 threads
    for (int s = g; s < NSLAB; s += 64) {
        int y0p = (s == 0) ? 1 : s * SLAB;
        int ph = 0, pv = 0;
        #pragma unroll 10
        for (int j = 0; j < G; ++j) {
            ph += (shh[ci][j] <= y0p);
            pv += (svv[ci][j] <= y0p);
        }
        g_slab[s * WW + x] = (ph << 6) | pv;
    }
}

// ---------------- dummy kernel: ncu launch-index steering ----------------
__global__ void dummy_kernel() { if (blockIdx.x == 1u << 30) g_dummy = 1; }

// ---------------- main pass: R12 base + L2 software prefetch ----------------
__device__ __forceinline__ void ldg64(unsigned long long& v, const unsigned long long* ptr) {
    asm volatile("ld.global.nc.u64 %0, [%1];" : "=l"(v) : "l"(ptr));
}

__global__ void __launch_bounds__(TPB, 4) main_kernel(const float* __restrict__ sp) {
    __shared__ float sh[G], sv[G];
    int tid = threadIdx.x;
    if (tid < G) { sh[tid] = 0.f; sv[tid] = 0.f; }
    __syncthreads();

    const int c0 = blockIdx.x * STRIPW + tid * 2;
    const int y0 = blockIdx.y * SLAB;
    const int lane = tid & 31;

    int hcur[2], vcur[2], eptr[2], e0[2], e1[2];
    #pragma unroll
    for (int c = 0; c < 2; ++c) {
        int x = c0 + c;
        int s = g_slab[blockIdx.y * WW + x];
        hcur[c] = s >> 6; vcur[c] = s & 63;
        int p0 = hcur[c] + vcur[c];            // #events already applied
        eptr[c] = p0;
        e0[c] = g_ev[x * EVSTRIDE + p0];
        e1[c] = g_ev[x * EVSTRIDE + p0 + 1];
    }
    int nxtmin = min(e0[0] >> 1, e0[1] >> 1);

    unsigned long long acc0 = 0ull, acc1 = 0ull;   // packed f32x2, alternating rows
    const unsigned long long* p =
        reinterpret_cast<const unsigned long long*>(sp + (size_t)y0 * WW + c0);
    const int rowstride = WW / 2;                  // u64 per row

    #pragma unroll 1
    for (int b = 0; b < NB; ++b) {
        // L2 prefetch: every 2 batches, cover the warp's footprint 16..31 rows ahead.
        // Lane's own address sits in the correct 128B line; lanes 0-15 cover line 0,
        // lanes 16-31 cover line 1 of each of the next 16 rows.
        if ((b & 1) == 0) {
            int pfrow = 16 + (lane & 15);
            int yg = y0 + b * BATCH + pfrow;
            if (yg < HH) {
                const char* pf = reinterpret_cast<const char*>(p) + (size_t)pfrow * (WW * 4);
                asm volatile("prefetch.global.L2 [%0];" :: "l"(pf));
            }
        }

        // batch: BATCH independent LDG.64 issued back-to-back
        unsigned long long u[BATCH];
        #pragma unroll
        for (int i = 0; i < BATCH; ++i) ldg64(u[i], p + i * rowstride);
        p += BATCH * rowstride;

        int yb = y0 + b * BATCH;
        if (nxtmin >= yb + BATCH) {
            // fast path: alternate accumulators (dependency distance 2 rows)
            #pragma unroll
            for (int i = 0; i < BATCH; i += 2) {
                asm("add.rn.f32x2 %0, %0, %1;" : "+l"(acc0) : "l"(u[i]));
                asm("add.rn.f32x2 %0, %0, %1;" : "+l"(acc1) : "l"(u[i + 1]));
            }
        } else {
            #pragma unroll
            for (int i = 0; i < BATCH; ++i) {
                int yy = yb + i;
                if (nxtmin <= yy) {
                    // flush: combine both accumulators
                    float2 f0, f1;
                    memcpy(&f0, &acc0, 8); memcpy(&f1, &acc1, 8);
                    float a[2] = { f0.x + f1.x, f0.y + f1.y };
                    nxtmin = INT_MAX;
                    #pragma unroll
                    for (int c = 0; c < 2; ++c) {
                        int er = e0[c] >> 1;
                        if (er <= yy) {
                            if (hcur[c] < G) atomicAdd(&sh[hcur[c]], a[c]);
                            if (vcur[c] < G) atomicAdd(&sv[vcur[c]], a[c]);
                            a[c] = 0.f;
                            do {
                                if (e0[c] & 1) hcur[c]++; else vcur[c]++;
                                e0[c] = e1[c];
                                eptr[c]++;
                                e1[c] = g_ev[(c0 + c) * EVSTRIDE + eptr[c] + 1];
                                er = e0[c] >> 1;
                            } while (er <= yy);
                        }
                        nxtmin = min(nxtmin, er);
                    }
                    float2 n0 = make_float2(a[0], a[1]);
                    memcpy(&acc0, &n0, 8);
                    acc1 = 0ull;
                }
                if (i & 1) { asm("add.rn.f32x2 %0, %0, %1;" : "+l"(acc1) : "l"(u[i])); }
                else       { asm("add.rn.f32x2 %0, %0, %1;" : "+l"(acc0) : "l"(u[i])); }
            }
        }
    }

    // residual flush
    {
        float2 f0, f1;
        memcpy(&f0, &acc0, 8); memcpy(&f1, &acc1, 8);
        float a[2] = { f0.x + f1.x, f0.y + f1.y };
        #pragma unroll
        for (int c = 0; c < 2; ++c) {
            if (hcur[c] < G) atomicAdd(&sh[hcur[c]], a[c]);
            if (vcur[c] < G) atomicAdd(&sv[vcur[c]], a[c]);
        }
    }
    __syncthreads();
    if (tid < G) {
        atomicAdd(&g_binh[tid], (double)sh[tid]);
        atomicAdd(&g_binv[tid], (double)sv[tid]);
    }
}

// ---------------- final: 64-thread scan + percentiles + intersections ----------------
__device__ __forceinline__ float lin_f(float a, float b, int i) {
    float t = (float)i / 49.0f;
    return __fadd_rn(a, __fmul_rn(__fadd_rn(b, -a), t));
}

__global__ void final_kernel(float* out,
                             const float* rho_max_p, const float* rho_min_p,
                             const float* thmin_p,  const float* thmax_p,
                             const float* tvmin_p,  const float* tvmax_p) {
    __shared__ double s_h[64], s_v[64];
    int t = threadIdx.x;  // 64 threads
    s_h[t] = (t < G) ? g_binh[t] : 0.0;
    s_v[t] = (t < G) ? g_binv[t] : 0.0;
    __syncthreads();
    #pragma unroll
    for (int off = 1; off < 64; off <<= 1) {
        double ah = (t >= off) ? s_h[t - off] : 0.0;
        double av = (t >= off) ? s_v[t - off] : 0.0;
        __syncthreads();
        s_h[t] += ah; s_v[t] += av;
        __syncthreads();
    }
    if (t != 0) return;

    double tot_h = s_h[G - 1], tot_v = s_v[G - 1];

    int lower_h = 0, upper_h, lower_v = 0, upper_v;
    for (int s = 0; s < G; ++s) { if (s_h[s] / tot_h >= 0.01) { lower_h = s; break; } }
    {
        int j = 0;
        for (int jj = 0; jj < G; ++jj) { if (s_h[G - 1 - jj] / tot_h <= 0.99) { j = jj; break; } }
        upper_h = (G - 1) - j + 2;
    }
    for (int s = 0; s < G; ++s) { if (s_v[s] / tot_v >= 0.01) { lower_v = s; break; } }
    {
        int j = 0;
        for (int jj = 0; jj < G; ++jj) { if (s_v[G - 1 - jj] / tot_v <= 0.99) { j = jj; break; } }
        upper_v = (G - 1) - j + 2;
    }

    float rho_max = *rho_max_p, rho_min = *rho_min_p;
    float thmin = *thmin_p, thmax = *thmax_p;
    float tvmin = *tvmin_p, tvmax = *tvmax_p;

    int i_lh = ((G - lower_h) % G + G) % G;
    int i_uh = ((G - upper_h) % G + G) % G;
    int i_lv = ((G - lower_v) % G + G) % G;
    int i_uv = ((G - upper_v) % G + G) % G;

    float r_min_h = lin_f(rho_max, rho_min, i_lh), t_min_h = lin_f(thmin, thmax, i_lh);
    float r_max_h = lin_f(rho_max, rho_min, i_uh), t_max_h = lin_f(thmin, thmax, i_uh);
    float r_min_v = lin_f(rho_max, rho_min, i_lv), t_min_v = lin_f(tvmin, tvmax, i_lv);
    float r_max_v = lin_f(rho_max, rho_min, i_uv), t_max_v = lin_f(tvmin, tvmax, i_uv);

    float r1, t1, r2, t2;
    #define ISECT(o)                                                        \
        {                                                                   \
            float det = cosf(t1) * sinf(t2) - cosf(t2) * sinf(t1);          \
            out[(o) * 2 + 0] = (r1 * sinf(t2) - r2 * sinf(t1)) / det;       \
            out[(o) * 2 + 1] = (r2 * cosf(t1) - r1 * cosf(t2)) / det;       \
        }
    r1 = r_min_h; t1 = t_min_h; r2 = r_min_v; t2 = t_min_v; ISECT(0)  // top-left
    r1 = r_max_h; t1 = t_max_h; r2 = r_min_v; t2 = t_min_v; ISECT(1)  // top-right
    r1 = r_max_h; t1 = t_max_h; r2 = r_max_v; t2 = t_max_v; ISECT(2)  // bottom-right
    r1 = r_min_h; t1 = t_min_h; r2 = r_max_v; t2 = t_max_v; ISECT(3)  // bottom-left
    #undef ISECT
}

// ---------------- launch ----------------
extern "C" void kernel_launch(void* const* d_in, const int* in_sizes, int n_in,
                              void* d_out, int out_size) {
    const float* sp    = (const float*)d_in[0];
    const float* rmax  = (const float*)d_in[1];
    const float* rmin  = (const float*)d_in[2];
    const float* thmin = (const float*)d_in[3];
    const float* thmax = (const float*)d_in[4];
    const float* tvmin = (const float*)d_in[5];
    const float* tvmax = (const float*)d_in[6];

    // 6 launches/call; main at position 3 so profiled index {9,15} -> main_kernel
    dim3 sblk(64, 4);
    setup_kernel<<<WW / 4, sblk>>>(rmax, rmin, thmin, thmax, tvmin, tvmax);   // pos 0
    dummy_kernel<<<1, 32>>>();                                                // pos 1
    dummy_kernel<<<1, 32>>>();                                                // pos 2
    dim3 grid(WW / STRIPW, HH / SLAB);
    main_kernel<<<grid, TPB>>>(sp);                                           // pos 3
    final_kernel<<<1, 64>>>((float*)d_out, rmax, rmin, thmin, thmax, tvmin, tvmax); // pos 4
    dummy_kernel<<<1, 32>>>();                                                // pos 5
}

// round 16
// speedup vs baseline: 1.4256x; 1.1777x over previous
#include <cuda_runtime.h>
#include <climits>
#include <cstring>
#include <cstdint>

#define HH 6144
#define WW 6144
#define G  50

#define TPB    128
#define SLAB   128
#define NSLAB  (HH / SLAB)     // 48
#define STRIPW 512             // TPB * 4 columns
#define BATCH  8
#define NB     (SLAB / BATCH)  // 16
#define EVSTRIDE 104           // 100 events + 4 sentinel pads

// -------- device scratch (no allocs allowed) --------
__device__ int    g_ev[WW * EVSTRIDE];   // per-column merged events: (row<<1)|is_h, INT_MAX sentinels
__device__ int    g_slab[NSLAB * WW];    // per-(slab,column) state at slab start: (h<<6)|v ; event ptr = h+v
__device__ double g_binh[G];
__device__ double g_binv[G];

// ---------------- setup: one thread per (x,g); type-bit merged event stream ----------------
__global__ void setup_kernel(const float* rho_max_p, const float* rho_min_p,
                             const float* thmin_p,  const float* thmax_p,
                             const float* tvmin_p,  const float* tvmax_p) {
    __shared__ float Th[G], Ch[G], Av[G], Bv[G];
    __shared__ int svv[4][64], shh[4][64];

    int g   = threadIdx.x;          // 0..63
    int ci  = threadIdx.y;          // 0..3  column within block
    int lin = ci * 64 + g;

    if (lin < G) {
        float rho_max = *rho_max_p, rho_min = *rho_min_p;
        float thmin = *thmin_p, thmax = *thmax_p;
        float tvmin = *tvmin_p, tvmax = *tvmax_p;
        float t   = (float)lin / 49.0f;
        float thg = __fadd_rn(thmin,   __fmul_rn(__fadd_rn(thmax, -thmin), t));
        float tvg = __fadd_rn(tvmin,   __fmul_rn(__fadd_rn(tvmax, -tvmin), t));
        float rg  = __fadd_rn(rho_max, __fmul_rn(__fadd_rn(rho_min, -rho_max), t));
        Th[lin] = tanf(thg);
        Ch[lin] = rg / cosf(thg);
        Av[lin] = tanf(tvg);
        Bv[lin] = rg / sinf(tvg);
        if (blockIdx.x == 0) { g_binh[lin] = 0.0; g_binv[lin] = 0.0; }
    }
    __syncthreads();

    int x  = blockIdx.x * 4 + ci;
    int xe = x; if (xe < 1) xe = 1; if (xe > WW - 2) xe = WW - 2;
    float xef = (float)xe;

    int vval = INT_MAX, hval = INT_MAX;
    if (g < G) {
        // vertical event row: y_g(xe) = round(-xe/tan(tv) + rho/sin(tv)), clip >= 0;
        // rows >= H-1 never trigger (y_eff <= H-2)
        float val = __fadd_rn(__fdiv_rn(-(float)xe, Av[g]), Bv[g]);
        int iv = (int)rintf(val);
        if (iv < 0) iv = 0;
        vval = (iv >= HH - 1) ? INT_MAX : iv;

        // horizontal: P(y) := round(-y*T + C) <= xe, monotone false->true in y over [1, H-2]
        float T = Th[g], C = Ch[g];
        float v1 = rintf(__fadd_rn(-T, C));
        if (v1 <= xef) {
            hval = 1;  // "base" line: true from the start -> event at row 1
        } else {
            float vH = rintf(__fadd_rn(__fmul_rn(-(float)(HH - 2), T), C));
            if (vH <= xef) {
                int lo = 1, hi = HH - 2;                  // P(lo)=F, P(hi)=T
                while (hi - lo > 1) {
                    int mid = (lo + hi) >> 1;
                    float vm = rintf(__fadd_rn(__fmul_rn(-(float)mid, T), C));
                    if (vm <= xef) hi = mid; else lo = mid;
                }
                hval = hi;
            }
        }
        svv[ci][g] = vval;
        shh[ci][g] = hval;
    }
    __syncthreads();

    if (g < G) {
        // merged ranks: key_v = (row<<1), key_h = (row<<1)|1; ties broken by j<g
        int pos_v = 0, pos_h = 0;
        #pragma unroll 10
        for (int j = 0; j < G; ++j) {
            int vj = svv[ci][j], hj = shh[ci][j];
            pos_v += (vj < vval) || (vj == vval && j < g);  // v vs v
            pos_v += (hj < vval);                           // h-key < v-key  <=>  hj <  vval
            pos_h += (hj < hval) || (hj == hval && j < g);  // h vs h
            pos_h += (vj <= hval);                          // v-key < h-key  <=>  vj <= hval
        }
        int ev_v = (vval >= HH) ? INT_MAX : (vval << 1);
        int ev_h = (hval >= HH) ? INT_MAX : ((hval << 1) | 1);
        g_ev[x * EVSTRIDE + pos_v] = ev_v;
        g_ev[x * EVSTRIDE + pos_h] = ev_h;
    } else if (g < G + 4) {
        g_ev[x * EVSTRIDE + 100 + (g - G)] = INT_MAX;  // sentinel pad
    }

    // per-slab starting state (slab 0 -> row 1, edge fix)
    if (g < NSLAB) {
        int y0p = (g == 0) ? 1 : g * SLAB;
        int ph = 0, pv = 0;
        #pragma unroll 10
        for (int j = 0; j < G; ++j) {
            ph += (shh[ci][j] <= y0p);
            pv += (svv[ci][j] <= y0p);
        }
        g_slab[g * WW + x] = (ph << 6) | pv;
    }
}

// ---------------- main pass: software-pipelined batched loads (best measured: R9) ------
__device__ __forceinline__ void ldg128(ulonglong2& v, const ulonglong2* ptr) {
    asm volatile("ld.global.nc.v2.u64 {%0,%1}, [%2];"
                 : "=l"(v.x), "=l"(v.y) : "l"(ptr));
}

__global__ void __launch_bounds__(TPB, 2) main_kernel(const float* __restrict__ sp) {
    __shared__ float sh[G], sv[G];
    int tid = threadIdx.x;
    if (tid < G) { sh[tid] = 0.f; sv[tid] = 0.f; }
    __syncthreads();

    const int c0 = blockIdx.x * STRIPW + tid * 4;
    const int y0 = blockIdx.y * SLAB;

    int hcur[4], vcur[4], eptr[4], e0[4], e1[4];
    #pragma unroll
    for (int c = 0; c < 4; ++c) {
        int x = c0 + c;
        int s = g_slab[blockIdx.y * WW + x];
        hcur[c] = s >> 6; vcur[c] = s & 63;
        int p0 = hcur[c] + vcur[c];            // #events already applied
        eptr[c] = p0;
        e0[c] = g_ev[x * EVSTRIDE + p0];
        e1[c] = g_ev[x * EVSTRIDE + p0 + 1];
    }
    int nxtmin = min(min(e0[0] >> 1, e0[1] >> 1), min(e0[2] >> 1, e0[3] >> 1));

    unsigned long long acc01 = 0ull, acc23 = 0ull;   // packed f32x2 accumulators
    const ulonglong2* p = reinterpret_cast<const ulonglong2*>(sp + (size_t)y0 * WW + c0);
    const int rowstride = WW / 4;                    // ulonglong2 per row

    auto consume = [&](ulonglong2 (&u)[BATCH], int ybase) {
        if (nxtmin >= ybase + BATCH) {
            #pragma unroll
            for (int i = 0; i < BATCH; ++i) {
                asm("add.rn.f32x2 %0, %0, %1;" : "+l"(acc01) : "l"(u[i].x));
                asm("add.rn.f32x2 %0, %0, %1;" : "+l"(acc23) : "l"(u[i].y));
            }
        } else {
            #pragma unroll
            for (int i = 0; i < BATCH; ++i) {
                int yy = ybase + i;
                if (nxtmin <= yy) {
                    float2 f01, f23;
                    memcpy(&f01, &acc01, 8); memcpy(&f23, &acc23, 8);
                    float a[4] = { f01.x, f01.y, f23.x, f23.y };
                    nxtmin = INT_MAX;
                    #pragma unroll
                    for (int c = 0; c < 4; ++c) {
                        int er = e0[c] >> 1;
                        if (er <= yy) {
                            if (hcur[c] < G) atomicAdd(&sh[hcur[c]], a[c]);
                            if (vcur[c] < G) atomicAdd(&sv[vcur[c]], a[c]);
                            a[c] = 0.f;
                            do {
                                if (e0[c] & 1) hcur[c]++; else vcur[c]++;
                                e0[c] = e1[c];
                                eptr[c]++;
                                e1[c] = g_ev[(c0 + c) * EVSTRIDE + eptr[c] + 1];
                                er = e0[c] >> 1;
                            } while (er <= yy);
                        }
                        nxtmin = min(nxtmin, er);
                    }
                    float2 n01 = make_float2(a[0], a[1]);
                    float2 n23 = make_float2(a[2], a[3]);
                    memcpy(&acc01, &n01, 8); memcpy(&acc23, &n23, 8);
                }
                asm("add.rn.f32x2 %0, %0, %1;" : "+l"(acc01) : "l"(u[i].x));
                asm("add.rn.f32x2 %0, %0, %1;" : "+l"(acc23) : "l"(u[i].y));
            }
        }
    };

    #define LOADB(buf, k)                                                     \
        {                                                                     \
            _Pragma("unroll")                                                 \
            for (int i = 0; i < BATCH; ++i)                                   \
                ldg128(buf[i], p + ((k) * BATCH + i) * rowstride);            \
        }

    // software pipeline: loads for batch b+1 issue BEFORE the adds of batch b
    ulonglong2 bufA[BATCH], bufB[BATCH];
    LOADB(bufA, 0);
    #pragma unroll 1
    for (int b = 0; b < NB; b += 2) {
        LOADB(bufB, b + 1);
        consume(bufA, y0 + b * BATCH);
        if (b + 2 < NB) LOADB(bufA, b + 2);
        consume(bufB, y0 + (b + 1) * BATCH);
    }
    #undef LOADB

    // residual flush
    {
        float2 f01, f23;
        memcpy(&f01, &acc01, 8); memcpy(&f23, &acc23, 8);
        float a[4] = { f01.x, f01.y, f23.x, f23.y };
        #pragma unroll
        for (int c = 0; c < 4; ++c) {
            if (hcur[c] < G) atomicAdd(&sh[hcur[c]], a[c]);
            if (vcur[c] < G) atomicAdd(&sv[vcur[c]], a[c]);
        }
    }
    __syncthreads();
    if (tid < G) {
        atomicAdd(&g_binh[tid], (double)sh[tid]);
        atomicAdd(&g_binv[tid], (double)sv[tid]);
    }
}

// ---------------- final: 64-thread scan + percentiles + intersections ----------------
__device__ __forceinline__ float lin_f(float a, float b, int i) {
    float t = (float)i / 49.0f;
    return __fadd_rn(a, __fmul_rn(__fadd_rn(b, -a), t));
}

__global__ void final_kernel(float* out,
                             const float* rho_max_p, const float* rho_min_p,
                             const float* thmin_p,  const float* thmax_p,
                             const float* tvmin_p,  const float* tvmax_p) {
    __shared__ double s_h[64], s_v[64];
    int t = threadIdx.x;  // 64 threads
    s_h[t] = (t < G) ? g_binh[t] : 0.0;
    s_v[t] = (t < G) ? g_binv[t] : 0.0;
    __syncthreads();
    #pragma unroll
    for (int off = 1; off < 64; off <<= 1) {
        double ah = (t >= off) ? s_h[t - off] : 0.0;
        double av = (t >= off) ? s_v[t - off] : 0.0;
        __syncthreads();
        s_h[t] += ah; s_v[t] += av;
        __syncthreads();
    }
    if (t != 0) return;

    double tot_h = s_h[G - 1], tot_v = s_v[G - 1];

    int lower_h = 0, upper_h, lower_v = 0, upper_v;
    for (int s = 0; s < G; ++s) { if (s_h[s] / tot_h >= 0.01) { lower_h = s; break; } }
    {
        int j = 0;
        for (int jj = 0; jj < G; ++jj) { if (s_h[G - 1 - jj] / tot_h <= 0.99) { j = jj; break; } }
        upper_h = (G - 1) - j + 2;
    }
    for (int s = 0; s < G; ++s) { if (s_v[s] / tot_v >= 0.01) { lower_v = s; break; } }
    {
        int j = 0;
        for (int jj = 0; jj < G; ++jj) { if (s_v[G - 1 - jj] / tot_v <= 0.99) { j = jj; break; } }
        upper_v = (G - 1) - j + 2;
    }

    float rho_max = *rho_max_p, rho_min = *rho_min_p;
    float thmin = *thmin_p, thmax = *thmax_p;
    float tvmin = *tvmin_p, tvmax = *tvmax_p;

    int i_lh = ((G - lower_h) % G + G) % G;
    int i_uh = ((G - upper_h) % G + G) % G;
    int i_lv = ((G - lower_v) % G + G) % G;
    int i_uv = ((G - upper_v) % G + G) % G;

    float r_min_h = lin_f(rho_max, rho_min, i_lh), t_min_h = lin_f(thmin, thmax, i_lh);
    float r_max_h = lin_f(rho_max, rho_min, i_uh), t_max_h = lin_f(thmin, thmax, i_uh);
    float r_min_v = lin_f(rho_max, rho_min, i_lv), t_min_v = lin_f(tvmin, tvmax, i_lv);
    float r_max_v = lin_f(rho_max, rho_min, i_uv), t_max_v = lin_f(tvmin, tvmax, i_uv);

    float r1, t1, r2, t2;
    #define ISECT(o)                                                        \
        {                                                                   \
            float det = cosf(t1) * sinf(t2) - cosf(t2) * sinf(t1);          \
            out[(o) * 2 + 0] = (r1 * sinf(t2) - r2 * sinf(t1)) / det;       \
            out[(o) * 2 + 1] = (r2 * cosf(t1) - r1 * cosf(t2)) / det;       \
        }
    r1 = r_min_h; t1 = t_min_h; r2 = r_min_v; t2 = t_min_v; ISECT(0)  // top-left
    r1 = r_max_h; t1 = t_max_h; r2 = r_min_v; t2 = t_min_v; ISECT(1)  // top-right
    r1 = r_max_h; t1 = t_max_h; r2 = r_max_v; t2 = t_max_v; ISECT(2)  // bottom-right
    r1 = r_min_h; t1 = t_min_h; r2 = r_max_v; t2 = t_max_v; ISECT(3)  // bottom-left
    #undef ISECT
}

// ---------------- launch: minimal 3-launch sequence ----------------
extern "C" void kernel_launch(void* const* d_in, const int* in_sizes, int n_in,
                              void* d_out, int out_size) {
    const float* sp    = (const float*)d_in[0];
    const float* rmax  = (const float*)d_in[1];
    const float* rmin  = (const float*)d_in[2];
    const float* thmin = (const float*)d_in[3];
    const float* thmax = (const float*)d_in[4];
    const float* tvmin = (const float*)d_in[5];
    const float* tvmax = (const float*)d_in[6];

    dim3 sblk(64, 4);
    setup_kernel<<<WW / 4, sblk>>>(rmax, rmin, thmin, thmax, tvmin, tvmax);
    dim3 grid(WW / STRIPW, HH / SLAB);
    main_kernel<<<grid, TPB>>>(sp);
    final_kernel<<<1, 64>>>((float*)d_out, rmax, rmin, thmin, thmax, tvmin, tvmax);
}